// round 15
// baseline (speedup 1.0000x reference)
#include <cuda_runtime.h>
#include <cstdint>

// Problem shape (fixed by the dataset):
//   features:        (BS=4, C=64, P=12000) float32
//   x_orig_indices:  (BS, P) int32  (JAX x64 disabled: "int64" is silently int32)
//   y_orig_indices:  (BS, P) int32
//   output pseudo:   (BS, C, NY=440, NX=500) float32
#define BS     4
#define CCH    64
#define NP     12000
#define NXP    500
#define NYP    440
#define CELLS  (NXP * NYP)          // 220000
#define CELLS8 (CELLS / 8)          // 27500 cell8-groups per batch
#define NWORDS ((CELLS8 + 31) / 32) // 860 bitmap words per batch

#define TCHUNK  8192                // cells per tile (32KB fp32)
#define NTILE   ((CELLS + TCHUNK - 1) / TCHUNK)  // 27 (last tile = 7008 cells)
#define GRP_PER_TILE (TCHUNK / 8)   // 1024 cell8-groups per tile

// Scratch (allocation-free device globals).
__device__ int            g_winner[BS * CELLS];   // (p+1) or 0; reset by pack
__device__ unsigned short g_w16[BS * CELLS];      // compressed winner
__device__ unsigned int   g_bitmap[BS * NWORDS];  // 1 bit per cell8 group

// ---------------------------------------------------------------------------
// Phase 1: winner pass — JAX sequential .set semantics == last p wins == max p.
// Also zeroes the bitmap (ordered before pack's atomicOr by kernel boundary).
// ---------------------------------------------------------------------------
__global__ void winner_kernel(const int* __restrict__ xi,
                              const int* __restrict__ yi) {
    int i = blockIdx.x * blockDim.x + threadIdx.x;
    if (i < BS * NWORDS) g_bitmap[i] = 0u;
    if (i >= BS * NP) return;
    int b = i / NP;
    int p = i - b * NP;

    int x = xi[i];
    int y = yi[i];
    // jnp.clip semantics
    x = x < 0 ? 0 : (x >= NXP ? NXP - 1 : x);
    y = y < 0 ? 0 : (y >= NYP ? NYP - 1 : y);
    int cell = y * NXP + x;

    atomicMax(&g_winner[b * CELLS + cell], p + 1);
}

// ---------------------------------------------------------------------------
// Phase 2: pack int32 winner -> u16 + bitmap bit per cell8 group; reset the
// int32 winner for the next launch (sole reader -> replay-safe).
// ---------------------------------------------------------------------------
__global__ void pack_kernel() {
    const int n8 = BS * CELLS8;        // 110000
    int i = blockIdx.x * blockDim.x + threadIdx.x;
    if (i >= n8) return;
    int b     = i / CELLS8;
    int group = i - b * CELLS8;

    int4* wp = reinterpret_cast<int4*>(g_winner + b * CELLS) + group * 2;
    int4 w0 = wp[0];
    int4 w1 = wp[1];
    wp[0] = make_int4(0, 0, 0, 0);     // reset for next replay
    wp[1] = make_int4(0, 0, 0, 0);

    uint4 s;
    s.x = (unsigned int)(w0.x & 0xFFFF) | ((unsigned int)w0.y << 16);
    s.y = (unsigned int)(w0.z & 0xFFFF) | ((unsigned int)w0.w << 16);
    s.z = (unsigned int)(w1.x & 0xFFFF) | ((unsigned int)w1.y << 16);
    s.w = (unsigned int)(w1.z & 0xFFFF) | ((unsigned int)w1.w << 16);
    reinterpret_cast<uint4*>(g_w16 + b * CELLS)[group] = s;

    if (s.x | s.y | s.z | s.w)
        atomicOr(&g_bitmap[b * NWORDS + (group >> 5)], 1u << (group & 31));
}

// ---------------------------------------------------------------------------
// Phase 3: TMA-store gather, one 32KB tile per block, SINGLE-PASS fill.
// vs R14 (60.7us): no separate smem-zero pass (each thread writes all of its
// 4 groups: zeros or gathered values), one __syncthreads instead of three,
// 2x bigger tiles -> half the blocks, per-block overhead amortized 2x.
// Stores leave via cp.async.bulk (async proxy, bypasses the L1TEX store
// wavefront wall that pins STG gathers at ~56us).
// Grid (27, 256): consecutive blocks sweep planes linearly (best DRAM order).
// ~7 resident CTAs/SM overlap fill phases with store drains.
// ---------------------------------------------------------------------------
__global__ void __launch_bounds__(256)
tma_gather_kernel(const float* __restrict__ feat,
                  float* __restrict__ out) {
    __shared__ __align__(16) float tile[TCHUNK];   // 32KB

    const int chunk = blockIdx.x;                  // tile within plane
    const int bc    = blockIdx.y;                  // plane = b*CCH + c
    const int b     = bc >> 6;
    const int cell0 = chunk * TCHUNK;
    const int ncell = min(TCHUNK, CELLS - cell0);  // 8192 or 7008 (mult of 8)
    const int ng    = ncell >> 3;                  // 1024 or 876 groups
    const int g0    = cell0 >> 3;

    // Single-pass fill: every group gets written (zeros or gathered values).
    const float* frow = feat + (size_t)bc * NP;
    const float4 z = make_float4(0.f, 0.f, 0.f, 0.f);
    #pragma unroll
    for (int k = 0; k < GRP_PER_TILE / 256; k++) { // 4 iters
        const int g = threadIdx.x + k * 256;
        if (g >= ng) break;
        const int group = g0 + g;
        float4* dst = reinterpret_cast<float4*>(tile + g * 8);

        unsigned int word = __ldg(&g_bitmap[b * NWORDS + (group >> 5)]);
        if (!((word >> (group & 31)) & 1u)) {
            dst[0] = z;
            dst[1] = z;
        } else {
            uint4 w = __ldg(reinterpret_cast<const uint4*>(g_w16 + b * CELLS) + group);
            int p0 = (int)(w.x & 0xFFFFu), p1 = (int)(w.x >> 16);
            int p2 = (int)(w.y & 0xFFFFu), p3 = (int)(w.y >> 16);
            int p4 = (int)(w.z & 0xFFFFu), p5 = (int)(w.z >> 16);
            int p6 = (int)(w.w & 0xFFFFu), p7 = (int)(w.w >> 16);
            float4 v0, v1;
            v0.x = p0 ? __ldg(frow + p0 - 1) : 0.f;
            v0.y = p1 ? __ldg(frow + p1 - 1) : 0.f;
            v0.z = p2 ? __ldg(frow + p2 - 1) : 0.f;
            v0.w = p3 ? __ldg(frow + p3 - 1) : 0.f;
            v1.x = p4 ? __ldg(frow + p4 - 1) : 0.f;
            v1.y = p5 ? __ldg(frow + p5 - 1) : 0.f;
            v1.z = p6 ? __ldg(frow + p6 - 1) : 0.f;
            v1.w = p7 ? __ldg(frow + p7 - 1) : 0.f;
            dst[0] = v0;
            dst[1] = v1;
        }
    }
    __syncthreads();

    // One bulk async store: tile SMEM -> global via the async proxy.
    if (threadIdx.x == 0) {
        uint32_t saddr;
        asm("{ .reg .u64 t; cvta.to.shared.u64 t, %1; cvt.u32.u64 %0, t; }"
            : "=r"(saddr) : "l"(tile));
        asm volatile("fence.proxy.async.shared::cta;" ::: "memory");
        asm volatile(
            "cp.async.bulk.global.shared::cta.bulk_group [%0], [%1], %2;"
            :: "l"(out + (size_t)bc * CELLS + cell0), "r"(saddr),
               "r"(ncell * 4)
            : "memory");
        asm volatile("cp.async.bulk.commit_group;" ::: "memory");
        // Must drain before the CTA (and its smem) retires.
        asm volatile("cp.async.bulk.wait_group 0;" ::: "memory");
    }
    __syncthreads();
}

// ---------------------------------------------------------------------------
extern "C" void kernel_launch(void* const* d_in, const int* in_sizes, int n_in,
                              void* d_out, int out_size) {
    const float* feat = (const float*)d_in[0];
    const int*   xi   = (const int*)d_in[1];
    const int*   yi   = (const int*)d_in[2];
    float* out = (float*)d_out;

    {   // winner pass (+ bitmap zeroing)
        int n = BS * NP;
        int threads = 256;
        int blocks = (n + threads - 1) / threads;
        winner_kernel<<<blocks, threads>>>(xi, yi);
    }
    {   // pack to u16 + bitmap + reset
        int n = BS * CELLS8;
        int threads = 256;
        int blocks = (n + threads - 1) / threads;
        pack_kernel<<<blocks, threads>>>();
    }
    {   // TMA-store gather: one 32KB tile per block, single-pass fill
        dim3 grid(NTILE, BS * CCH);   // (27, 256) = 6912 blocks
        tma_gather_kernel<<<grid, 256>>>(feat, out);
    }
}

// round 16
// speedup vs baseline: 1.0309x; 1.0309x over previous
#include <cuda_runtime.h>
#include <cstdint>

// Problem shape (fixed by the dataset):
//   features:        (BS=4, C=64, P=12000) float32
//   x_orig_indices:  (BS, P) int32  (JAX x64 disabled: "int64" is silently int32)
//   y_orig_indices:  (BS, P) int32
//   output pseudo:   (BS, C, NY=440, NX=500) float32
#define BS     4
#define CCH    64
#define NP     12000
#define NXP    500
#define NYP    440
#define CELLS  (NXP * NYP)          // 220000
#define CELLS8 (CELLS / 8)          // 27500 cell8-groups per batch
#define NWORDS ((CELLS8 + 31) / 32) // 860 bitmap words per batch

#define TCH    4096                 // cells per tile (16KB fp32) — R14-proven
#define NT     ((CELLS + TCH - 1) / TCH)   // 54 tiles/plane (tail = 2912)
#define NPAIR  (NT / 2)             // 27 tile-pairs per plane

// Scratch (allocation-free device globals).
__device__ int            g_winner[BS * CELLS];   // (p+1) or 0; reset by pack
__device__ unsigned short g_w16[BS * CELLS];      // compressed winner
__device__ unsigned int   g_bitmap[BS * NWORDS];  // 1 bit per cell8 group

// ---------------------------------------------------------------------------
// Phase 1: winner pass — JAX sequential .set semantics == last p wins == max p.
// Also zeroes the bitmap (ordered before pack's atomicOr by kernel boundary).
// ---------------------------------------------------------------------------
__global__ void winner_kernel(const int* __restrict__ xi,
                              const int* __restrict__ yi) {
    int i = blockIdx.x * blockDim.x + threadIdx.x;
    if (i < BS * NWORDS) g_bitmap[i] = 0u;
    if (i >= BS * NP) return;
    int b = i / NP;
    int p = i - b * NP;

    int x = xi[i];
    int y = yi[i];
    // jnp.clip semantics
    x = x < 0 ? 0 : (x >= NXP ? NXP - 1 : x);
    y = y < 0 ? 0 : (y >= NYP ? NYP - 1 : y);
    int cell = y * NXP + x;

    atomicMax(&g_winner[b * CELLS + cell], p + 1);
}

// ---------------------------------------------------------------------------
// Phase 2: pack int32 winner -> u16 + bitmap bit per cell8 group; reset the
// int32 winner for the next launch (sole reader -> replay-safe).
// ---------------------------------------------------------------------------
__global__ void pack_kernel() {
    const int n8 = BS * CELLS8;        // 110000
    int i = blockIdx.x * blockDim.x + threadIdx.x;
    if (i >= n8) return;
    int b     = i / CELLS8;
    int group = i - b * CELLS8;

    int4* wp = reinterpret_cast<int4*>(g_winner + b * CELLS) + group * 2;
    int4 w0 = wp[0];
    int4 w1 = wp[1];
    wp[0] = make_int4(0, 0, 0, 0);     // reset for next replay
    wp[1] = make_int4(0, 0, 0, 0);

    uint4 s;
    s.x = (unsigned int)(w0.x & 0xFFFF) | ((unsigned int)w0.y << 16);
    s.y = (unsigned int)(w0.z & 0xFFFF) | ((unsigned int)w0.w << 16);
    s.z = (unsigned int)(w1.x & 0xFFFF) | ((unsigned int)w1.y << 16);
    s.w = (unsigned int)(w1.z & 0xFFFF) | ((unsigned int)w1.w << 16);
    reinterpret_cast<uint4*>(g_w16 + b * CELLS)[group] = s;

    if (s.x | s.y | s.z | s.w)
        atomicOr(&g_bitmap[b * NWORDS + (group >> 5)], 1u << (group & 31));
}

// ---------------------------------------------------------------------------
// Phase 3: TMA-store gather, DOUBLE-BUFFERED pair of 16KB tiles per block.
// R14 structure preserved (dependency-free zero pass; sparse winner fill;
// 16KB bulk-store granularity via the async proxy, bypassing the L1TEX store
// wavefront wall). New vs R14: the buf0 drain is hidden behind the buf1
// fill; only the final drain is exposed.
// Grid (27, 256): consecutive blocks sweep planes linearly (best DRAM order).
// 32KB smem -> 7 resident CTAs/SM keep fills and drains overlapped.
// ---------------------------------------------------------------------------
__global__ void __launch_bounds__(256)
tma_gather_kernel(const float* __restrict__ feat,
                  float* __restrict__ out) {
    __shared__ __align__(16) float buf[2][TCH];    // 2 x 16KB

    const int pair = blockIdx.x;                   // tile-pair within plane
    const int bc   = blockIdx.y;                   // plane = b*CCH + c
    const int b    = bc >> 6;
    const float* frow = feat + (size_t)bc * NP;

    // Dependency-free zero burst over BOTH buffers (32KB).
    {
        float4* t4 = reinterpret_cast<float4*>(&buf[0][0]);
        const float4 z = make_float4(0.f, 0.f, 0.f, 0.f);
        #pragma unroll
        for (int k = 0; k < (2 * TCH / 4) / 256; k++)   // 8 iters
            t4[threadIdx.x + k * 256] = z;
    }
    __syncthreads();

    uint32_t saddr0;
    asm("{ .reg .u64 t; cvta.to.shared.u64 t, %1; cvt.u32.u64 %0, t; }"
        : "=r"(saddr0) : "l"(&buf[0][0]));

    #pragma unroll
    for (int half = 0; half < 2; half++) {
        const int tile  = pair * 2 + half;
        const int cell0 = tile * TCH;
        const int ncell = min(TCH, CELLS - cell0);  // 4096 or 2912 (mult of 8)
        const int ng    = ncell >> 3;
        const int g0    = cell0 >> 3;

        // Sparse winner fill into buf[half] (~35% of groups touched).
        for (int g = threadIdx.x; g < ng; g += 256) {
            const int group = g0 + g;
            unsigned int word = __ldg(&g_bitmap[b * NWORDS + (group >> 5)]);
            if (!((word >> (group & 31)) & 1u)) continue;

            uint4 w = __ldg(reinterpret_cast<const uint4*>(g_w16 + b * CELLS) + group);
            int p0 = (int)(w.x & 0xFFFFu), p1 = (int)(w.x >> 16);
            int p2 = (int)(w.y & 0xFFFFu), p3 = (int)(w.y >> 16);
            int p4 = (int)(w.z & 0xFFFFu), p5 = (int)(w.z >> 16);
            int p6 = (int)(w.w & 0xFFFFu), p7 = (int)(w.w >> 16);
            float4 v0, v1;
            v0.x = p0 ? __ldg(frow + p0 - 1) : 0.f;
            v0.y = p1 ? __ldg(frow + p1 - 1) : 0.f;
            v0.z = p2 ? __ldg(frow + p2 - 1) : 0.f;
            v0.w = p3 ? __ldg(frow + p3 - 1) : 0.f;
            v1.x = p4 ? __ldg(frow + p4 - 1) : 0.f;
            v1.y = p5 ? __ldg(frow + p5 - 1) : 0.f;
            v1.z = p6 ? __ldg(frow + p6 - 1) : 0.f;
            v1.w = p7 ? __ldg(frow + p7 - 1) : 0.f;
            float4* dst = reinterpret_cast<float4*>(&buf[half][g * 8]);
            dst[0] = v0;
            dst[1] = v1;
        }
        __syncthreads();

        // Commit this tile's bulk store; do NOT wait — the next half's fill
        // (different buffer) overlaps the drain.
        if (threadIdx.x == 0) {
            asm volatile("fence.proxy.async.shared::cta;" ::: "memory");
            asm volatile(
                "cp.async.bulk.global.shared::cta.bulk_group [%0], [%1], %2;"
                :: "l"(out + (size_t)bc * CELLS + cell0),
                   "r"(saddr0 + half * (TCH * 4)),
                   "r"(ncell * 4)
                : "memory");
            asm volatile("cp.async.bulk.commit_group;" ::: "memory");
        }
    }

    // Drain both stores before the CTA (and its smem) retires.
    if (threadIdx.x == 0)
        asm volatile("cp.async.bulk.wait_group 0;" ::: "memory");
    __syncthreads();
}

// ---------------------------------------------------------------------------
extern "C" void kernel_launch(void* const* d_in, const int* in_sizes, int n_in,
                              void* d_out, int out_size) {
    const float* feat = (const float*)d_in[0];
    const int*   xi   = (const int*)d_in[1];
    const int*   yi   = (const int*)d_in[2];
    float* out = (float*)d_out;

    {   // winner pass (+ bitmap zeroing)
        int n = BS * NP;
        int threads = 256;
        int blocks = (n + threads - 1) / threads;
        winner_kernel<<<blocks, threads>>>(xi, yi);
    }
    {   // pack to u16 + bitmap + reset
        int n = BS * CELLS8;
        int threads = 256;
        int blocks = (n + threads - 1) / threads;
        pack_kernel<<<blocks, threads>>>();
    }
    {   // TMA-store gather: double-buffered 16KB tile pairs
        dim3 grid(NPAIR, BS * CCH);   // (27, 256) = 6912 blocks
        tma_gather_kernel<<<grid, 256>>>(feat, out);
    }
}

// round 17
// speedup vs baseline: 1.0712x; 1.0391x over previous
#include <cuda_runtime.h>
#include <cstdint>

// Problem shape (fixed by the dataset):
//   features:        (BS=4, C=64, P=12000) float32
//   x_orig_indices:  (BS, P) int32  (JAX x64 disabled: "int64" is silently int32)
//   y_orig_indices:  (BS, P) int32
//   output pseudo:   (BS, C, NY=440, NX=500) float32
#define BS     4
#define CCH    64
#define NP     12000
#define NXP    500
#define NYP    440
#define CELLS  (NXP * NYP)          // 220000
#define CELLS8 (CELLS / 8)          // 27500 cell8-groups per batch
#define NWORDS ((CELLS8 + 31) / 32) // 860 bitmap words per batch

#define TCHUNK  2048                // cells per tile (8KB fp32) — R17 variable
#define NTILE   ((CELLS + TCHUNK - 1) / TCHUNK)  // 108 (last tile = 884..  -> 219*... )

// Scratch (allocation-free device globals).
__device__ int            g_winner[BS * CELLS];   // (p+1) or 0; reset by pack
__device__ unsigned short g_w16[BS * CELLS];      // compressed winner
__device__ unsigned int   g_bitmap[BS * NWORDS];  // 1 bit per cell8 group

// ---------------------------------------------------------------------------
// Phase 1: winner pass — JAX sequential .set semantics == last p wins == max p.
// Also zeroes the bitmap (ordered before pack's atomicOr by kernel boundary).
// ---------------------------------------------------------------------------
__global__ void winner_kernel(const int* __restrict__ xi,
                              const int* __restrict__ yi) {
    int i = blockIdx.x * blockDim.x + threadIdx.x;
    if (i < BS * NWORDS) g_bitmap[i] = 0u;
    if (i >= BS * NP) return;
    int b = i / NP;
    int p = i - b * NP;

    int x = xi[i];
    int y = yi[i];
    // jnp.clip semantics
    x = x < 0 ? 0 : (x >= NXP ? NXP - 1 : x);
    y = y < 0 ? 0 : (y >= NYP ? NYP - 1 : y);
    int cell = y * NXP + x;

    atomicMax(&g_winner[b * CELLS + cell], p + 1);
}

// ---------------------------------------------------------------------------
// Phase 2: pack int32 winner -> u16 + bitmap bit per cell8 group; reset the
// int32 winner for the next launch (sole reader -> replay-safe).
// ---------------------------------------------------------------------------
__global__ void pack_kernel() {
    const int n8 = BS * CELLS8;        // 110000
    int i = blockIdx.x * blockDim.x + threadIdx.x;
    if (i >= n8) return;
    int b     = i / CELLS8;
    int group = i - b * CELLS8;

    int4* wp = reinterpret_cast<int4*>(g_winner + b * CELLS) + group * 2;
    int4 w0 = wp[0];
    int4 w1 = wp[1];
    wp[0] = make_int4(0, 0, 0, 0);     // reset for next replay
    wp[1] = make_int4(0, 0, 0, 0);

    uint4 s;
    s.x = (unsigned int)(w0.x & 0xFFFF) | ((unsigned int)w0.y << 16);
    s.y = (unsigned int)(w0.z & 0xFFFF) | ((unsigned int)w0.w << 16);
    s.z = (unsigned int)(w1.x & 0xFFFF) | ((unsigned int)w1.y << 16);
    s.w = (unsigned int)(w1.z & 0xFFFF) | ((unsigned int)w1.w << 16);
    reinterpret_cast<uint4*>(g_w16 + b * CELLS)[group] = s;

    if (s.x | s.y | s.z | s.w)
        atomicOr(&g_bitmap[b * NWORDS + (group >> 5)], 1u << (group & 31));
}

// ---------------------------------------------------------------------------
// Phase 3: TMA-store gather — R14's exact structure, tile size halved to 8KB.
// block = 8KB tile of one plane: zero smem (dependency-free burst), sparse
// winner fill (bitmap fast-skip, w16 + L2-hot feat gathers), one bulk async
// store (async proxy -> bypasses the L1TEX store-wavefront wall), drain.
// Grid (108, 256) = 27648 blocks; high per-SM residency (8KB smem) gives
// fine-grained inter-CTA overlap of fill phases with TMA drains.
// ---------------------------------------------------------------------------
__global__ void __launch_bounds__(256)
tma_gather_kernel(const float* __restrict__ feat,
                  float* __restrict__ out) {
    __shared__ __align__(16) float tile[TCHUNK];   // 8KB

    const int chunk = blockIdx.x;                  // tile within plane
    const int bc    = blockIdx.y;                  // plane = b*CCH + c
    const int b     = bc >> 6;
    const int cell0 = chunk * TCHUNK;
    const int ncell = min(TCHUNK, CELLS - cell0);  // 2048 or 928 (mult of 8)

    // Zero the smem tile (dependency-free store burst).
    {
        float4* t4 = reinterpret_cast<float4*>(tile);
        const float4 z = make_float4(0.f, 0.f, 0.f, 0.f);
        #pragma unroll
        for (int k = 0; k < TCHUNK / 4 / 256; k++)  // 2 iters
            t4[threadIdx.x + k * 256] = z;
    }
    __syncthreads();

    // Overwrite winner cells. One thread per cell8 group (256 groups/tile).
    {
        const int g0 = cell0 >> 3;
        const int ng = ncell >> 3;                 // 256 or 116
        const float* frow = feat + (size_t)bc * NP;
        for (int g = threadIdx.x; g < ng; g += 256) {
            const int group = g0 + g;
            unsigned int word = __ldg(&g_bitmap[b * NWORDS + (group >> 5)]);
            if (!((word >> (group & 31)) & 1u)) continue;

            uint4 w = __ldg(reinterpret_cast<const uint4*>(g_w16 + b * CELLS) + group);
            int p0 = (int)(w.x & 0xFFFFu), p1 = (int)(w.x >> 16);
            int p2 = (int)(w.y & 0xFFFFu), p3 = (int)(w.y >> 16);
            int p4 = (int)(w.z & 0xFFFFu), p5 = (int)(w.z >> 16);
            int p6 = (int)(w.w & 0xFFFFu), p7 = (int)(w.w >> 16);
            float4 v0, v1;
            v0.x = p0 ? __ldg(frow + p0 - 1) : 0.f;
            v0.y = p1 ? __ldg(frow + p1 - 1) : 0.f;
            v0.z = p2 ? __ldg(frow + p2 - 1) : 0.f;
            v0.w = p3 ? __ldg(frow + p3 - 1) : 0.f;
            v1.x = p4 ? __ldg(frow + p4 - 1) : 0.f;
            v1.y = p5 ? __ldg(frow + p5 - 1) : 0.f;
            v1.z = p6 ? __ldg(frow + p6 - 1) : 0.f;
            v1.w = p7 ? __ldg(frow + p7 - 1) : 0.f;
            float4* dst = reinterpret_cast<float4*>(tile + g * 8);
            dst[0] = v0;
            dst[1] = v1;
        }
    }
    __syncthreads();

    // One bulk async store: 8KB (or tail) SMEM -> global, async proxy.
    if (threadIdx.x == 0) {
        uint32_t saddr;
        asm("{ .reg .u64 t; cvta.to.shared.u64 t, %1; cvt.u32.u64 %0, t; }"
            : "=r"(saddr) : "l"(tile));
        asm volatile("fence.proxy.async.shared::cta;" ::: "memory");
        asm volatile(
            "cp.async.bulk.global.shared::cta.bulk_group [%0], [%1], %2;"
            :: "l"(out + (size_t)bc * CELLS + cell0), "r"(saddr),
               "r"(ncell * 4)
            : "memory");
        asm volatile("cp.async.bulk.commit_group;" ::: "memory");
        // Must drain before the CTA (and its smem) retires.
        asm volatile("cp.async.bulk.wait_group 0;" ::: "memory");
    }
    __syncthreads();
}

// ---------------------------------------------------------------------------
extern "C" void kernel_launch(void* const* d_in, const int* in_sizes, int n_in,
                              void* d_out, int out_size) {
    const float* feat = (const float*)d_in[0];
    const int*   xi   = (const int*)d_in[1];
    const int*   yi   = (const int*)d_in[2];
    float* out = (float*)d_out;

    {   // winner pass (+ bitmap zeroing)
        int n = BS * NP;
        int threads = 256;
        int blocks = (n + threads - 1) / threads;
        winner_kernel<<<blocks, threads>>>(xi, yi);
    }
    {   // pack to u16 + bitmap + reset
        int n = BS * CELLS8;
        int threads = 256;
        int blocks = (n + threads - 1) / threads;
        pack_kernel<<<blocks, threads>>>();
    }
    {   // TMA-store gather: one 8KB tile per block
        dim3 grid(NTILE, BS * CCH);   // (108, 256) = 27648 blocks
        tma_gather_kernel<<<grid, 256>>>(feat, out);
    }
}